// round 10
// baseline (speedup 1.0000x reference)
#include <cuda_runtime.h>

// RandomShiftsAug == integer-shift gather with edge clamp.
// out[n,c,i,j] = x[n,c, clamp(i+dy,0,223), clamp(j+dx,0,223)], dx,dy in [-4,4].
//
// ILP=4: each thread produces 4 float4 outputs; all global loads are issued
// up front (load loop) before composition/stores, maximizing memory-level
// parallelism. Reads use aligned LDG.128 + image-uniform component select
// (r = dx & 3). Row-edge outputs use a scalar clamped fallback.

#define H 224
#define W 224
#define C 9
#define PAD 4
#define W4 (W / 4)                 // 56 float4 per row
#define PER_N (C * H * W4)         // 112896 float4 per image
#define ILP 4
#define TPB 256
#define CHUNK (TPB * ILP)          // 1024 outputs per block

__global__ __launch_bounds__(TPB) void shift_gather_kernel(
    const float* __restrict__ x,
    const int* __restrict__ shift,
    float* __restrict__ out)
{
    const int n  = blockIdx.y;
    const int dx = __ldg(shift + n * 2 + 0) - PAD;
    const int dy = __ldg(shift + n * 2 + 1) - PAD;
    const int r  = dx & 3;                       // image-uniform sub-word shift

    const int base = blockIdx.x * CHUNK + threadIdx.x;

    float4 q0[ILP];
    float4 q1[ILP];
    int edge_mask = 0;                           // bit k: q0[k] already final

    // ---- load phase: issue every global load before any compose/store ----
    #pragma unroll
    for (int k = 0; k < ILP; k++) {
        const int t = base + k * TPB;
        if (t >= PER_N) continue;                // only in the last grid.x block

        const int j4   = t % W4;
        const int rest = t / W4;
        const int i    = rest % H;
        const int c    = rest / H;

        int ri = i + dy;
        ri = ri < 0 ? 0 : (ri > H - 1 ? H - 1 : ri);

        const float* __restrict__ row =
            x + ((size_t)(n * C + c) * H + ri) * W;

        const int s = j4 * 4 + dx;               // first source column
        if (s >= 0 && s <= W - 4) {
            const float4* __restrict__ rw = (const float4*)row;
            const int w0 = s >> 2;
            q0[k] = __ldg(rw + w0);
            if (r != 0)
                q1[k] = __ldg(rw + w0 + 1);
        } else {
            // edge: scalar clamped gather, store final value into q0[k]
            int c0 = s + 0; c0 = c0 < 0 ? 0 : (c0 > W - 1 ? W - 1 : c0);
            int c1 = s + 1; c1 = c1 < 0 ? 0 : (c1 > W - 1 ? W - 1 : c1);
            int c2 = s + 2; c2 = c2 < 0 ? 0 : (c2 > W - 1 ? W - 1 : c2);
            int c3 = s + 3; c3 = c3 < 0 ? 0 : (c3 > W - 1 ? W - 1 : c3);
            q0[k].x = __ldg(row + c0);
            q0[k].y = __ldg(row + c1);
            q0[k].z = __ldg(row + c2);
            q0[k].w = __ldg(row + c3);
            edge_mask |= (1 << k);
        }
    }

    // ---- compose + store phase ----
    float4* __restrict__ o4 = reinterpret_cast<float4*>(out) + (size_t)n * PER_N;
    #pragma unroll
    for (int k = 0; k < ILP; k++) {
        const int t = base + k * TPB;
        if (t >= PER_N) continue;

        float4 v;
        if ((edge_mask >> k) & 1) {
            v = q0[k];
        } else if (r == 0) {
            v = q0[k];
        } else if (r == 1) {
            v = make_float4(q0[k].y, q0[k].z, q0[k].w, q1[k].x);
        } else if (r == 2) {
            v = make_float4(q0[k].z, q0[k].w, q1[k].x, q1[k].y);
        } else {
            v = make_float4(q0[k].w, q1[k].x, q1[k].y, q1[k].z);
        }
        o4[t] = v;
    }
}

extern "C" void kernel_launch(void* const* d_in, const int* in_sizes, int n_in,
                              void* d_out, int out_size)
{
    const float* x     = (const float*)d_in[0];
    const int*   shift = (const int*)d_in[1];
    float*       out   = (float*)d_out;

    dim3 grid((PER_N + CHUNK - 1) / CHUNK, 128);   // (111, 128)
    shift_gather_kernel<<<grid, TPB>>>(x, shift, out);
}

// round 11
// speedup vs baseline: 1.1937x; 1.1937x over previous
#include <cuda_runtime.h>

// RandomShiftsAug == integer-shift gather with edge clamp.
// out[n,c,i,j] = x[n,c, clamp(i+dy,0,223), clamp(j+dx,0,223)], dx,dy in [-4,4].
//
// R1 structure (4 scalar clamped LDGs + one float4 store per output) — the
// best-measured read path — with ILP=2: each thread produces 2 float4
// outputs 256 apart, all 8 loads issued before either store, doubling
// per-SM in-flight read bytes while keeping register count low enough for
// full occupancy.

#define H 224
#define W 224
#define C 9
#define PAD 4
#define W4 (W / 4)                 // 56 float4 per row
#define PER_N (C * H * W4)         // 112896 float4 per image
#define TPB 256
#define ILP 2
#define CHUNK (TPB * ILP)          // 512 outputs per block

__global__ __launch_bounds__(TPB) void shift_gather_kernel(
    const float* __restrict__ x,
    const int* __restrict__ shift,
    float* __restrict__ out)
{
    const int n  = blockIdx.y;
    const int dx = __ldg(shift + n * 2 + 0) - PAD;
    const int dy = __ldg(shift + n * 2 + 1) - PAD;

    // PER_N = 112896 = 220.5 * 512, so last block of each image is half-tail;
    // grid.x = ceil(PER_N/512) = 221 and we predicate on t < PER_N.
    const int base = blockIdx.x * CHUNK + threadIdx.x;

    const float* __restrict__ xn = x + (size_t)n * C * H * W;

    float4 v[ILP];

    // ---- load phase: all 8 scalar loads issued before any store ----
    #pragma unroll
    for (int k = 0; k < ILP; k++) {
        const int t = base + k * TPB;
        if (t >= PER_N) continue;

        const int j4   = t % W4;
        const int rest = t / W4;
        const int i    = rest % H;
        const int c    = rest / H;

        int ri = i + dy;
        ri = ri < 0 ? 0 : (ri > H - 1 ? H - 1 : ri);

        const float* __restrict__ row = xn + ((size_t)c * H + ri) * W;

        const int s = j4 * 4 + dx;
        int c0 = s + 0; c0 = c0 < 0 ? 0 : (c0 > W - 1 ? W - 1 : c0);
        int c1 = s + 1; c1 = c1 < 0 ? 0 : (c1 > W - 1 ? W - 1 : c1);
        int c2 = s + 2; c2 = c2 < 0 ? 0 : (c2 > W - 1 ? W - 1 : c2);
        int c3 = s + 3; c3 = c3 < 0 ? 0 : (c3 > W - 1 ? W - 1 : c3);

        v[k].x = __ldg(row + c0);
        v[k].y = __ldg(row + c1);
        v[k].z = __ldg(row + c2);
        v[k].w = __ldg(row + c3);
    }

    // ---- store phase ----
    float4* __restrict__ o4 = reinterpret_cast<float4*>(out) + (size_t)n * PER_N;
    #pragma unroll
    for (int k = 0; k < ILP; k++) {
        const int t = base + k * TPB;
        if (t < PER_N)
            o4[t] = v[k];
    }
}

extern "C" void kernel_launch(void* const* d_in, const int* in_sizes, int n_in,
                              void* d_out, int out_size)
{
    const float* x     = (const float*)d_in[0];
    const int*   shift = (const int*)d_in[1];
    float*       out   = (float*)d_out;

    dim3 grid((PER_N + CHUNK - 1) / CHUNK, 128);   // (221, 128)
    shift_gather_kernel<<<grid, TPB>>>(x, shift, out);
}

// round 13
// speedup vs baseline: 1.2096x; 1.0134x over previous
#include <cuda_runtime.h>

// RandomShiftsAug == integer-shift gather with edge clamp.
// out[n,c,i,j] = x[n,c, clamp(i+dy,0,223), clamp(j+dx,0,223)], dx,dy in [-4,4].
//
// Scalar clamped LDG read path (best measured) with ILP=3: each thread
// produces 3 float4 outputs spaced TPB apart; all 12 loads are issued before
// any store, maximizing per-SM in-flight read bytes. CHUNK=768 divides
// PER_N=112896 exactly (147 blocks/image) -> zero tail predication.

#define H 224
#define W 224
#define C 9
#define PAD 4
#define W4 (W / 4)                 // 56 float4 per row
#define PER_N (C * H * W4)         // 112896 float4 per image
#define TPB 256
#define ILP 3
#define CHUNK (TPB * ILP)          // 768; PER_N / 768 == 147 exactly

__global__ __launch_bounds__(TPB) void shift_gather_kernel(
    const float* __restrict__ x,
    const int* __restrict__ shift,
    float* __restrict__ out)
{
    const int n  = blockIdx.y;
    const int dx = __ldg(shift + n * 2 + 0) - PAD;
    const int dy = __ldg(shift + n * 2 + 1) - PAD;

    const int base = blockIdx.x * CHUNK + threadIdx.x;

    const float* __restrict__ xn = x + (size_t)n * C * H * W;

    float4 v[ILP];

    // ---- load phase: all 12 scalar loads issued before any store ----
    #pragma unroll
    for (int k = 0; k < ILP; k++) {
        const int t = base + k * TPB;

        const int j4   = t % W4;
        const int rest = t / W4;
        const int i    = rest % H;
        const int c    = rest / H;

        int ri = i + dy;
        ri = ri < 0 ? 0 : (ri > H - 1 ? H - 1 : ri);

        const float* __restrict__ row = xn + ((size_t)c * H + ri) * W;

        const int s = j4 * 4 + dx;
        int c0 = s + 0; c0 = c0 < 0 ? 0 : (c0 > W - 1 ? W - 1 : c0);
        int c1 = s + 1; c1 = c1 < 0 ? 0 : (c1 > W - 1 ? W - 1 : c1);
        int c2 = s + 2; c2 = c2 < 0 ? 0 : (c2 > W - 1 ? W - 1 : c2);
        int c3 = s + 3; c3 = c3 < 0 ? 0 : (c3 > W - 1 ? W - 1 : c3);

        v[k].x = __ldg(row + c0);
        v[k].y = __ldg(row + c1);
        v[k].z = __ldg(row + c2);
        v[k].w = __ldg(row + c3);
    }

    // ---- store phase ----
    float4* __restrict__ o4 = reinterpret_cast<float4*>(out) + (size_t)n * PER_N;
    #pragma unroll
    for (int k = 0; k < ILP; k++) {
        o4[base + k * TPB] = v[k];
    }
}

extern "C" void kernel_launch(void* const* d_in, const int* in_sizes, int n_in,
                              void* d_out, int out_size)
{
    const float* x     = (const float*)d_in[0];
    const int*   shift = (const int*)d_in[1];
    float*       out   = (float*)d_out;

    dim3 grid(PER_N / CHUNK, 128);   // (147, 128)
    shift_gather_kernel<<<grid, TPB>>>(x, shift, out);
}